// round 2
// baseline (speedup 1.0000x reference)
#include <cuda_runtime.h>

// Shapes fixed by setup_inputs()
#define B  64
#define T  1024
#define DQ 1024
#define DV 512
#define A  128
#define TC 128
#define NC (T / TC)

// Scratch (no allocation allowed)
__device__ float g_pq[B * A];
__device__ float g_scr_align[B * T];
__device__ float g_scr_ctx[B * DV];

// tanh via fast exp: tanh(x) = 1 - 2/(exp(2x)+1); stable at both tails
__device__ __forceinline__ float ftanh(float x) {
    return 1.0f - 2.0f / (1.0f + __expf(2.0f * x));
}

__global__ void __launch_bounds__(512) zero_ctx_kernel(float* ctx) {
    if (ctx == nullptr) ctx = g_scr_ctx;
    int i = blockIdx.x * blockDim.x + threadIdx.x;
    if (i < B * DV) ctx[i] = 0.0f;
}

// pq[b,a] = sum_k query[b,k] * Wq[a,k]   — warp per (b,a) row-dot, fully coalesced
__global__ void __launch_bounds__(256) pq_kernel(const float* __restrict__ query,
                                                 const float* __restrict__ Wq) {
    __shared__ float sq[DQ];
    int b = blockIdx.x;
    for (int i = threadIdx.x; i < DQ; i += blockDim.x) sq[i] = query[b * DQ + i];
    __syncthreads();

    int lane = threadIdx.x & 31;
    int warp = threadIdx.x >> 5;
    int nw = blockDim.x >> 5;   // 8 warps
    const float4* sq4 = reinterpret_cast<const float4*>(sq);
    for (int a = warp; a < A; a += nw) {
        const float4* w4 = reinterpret_cast<const float4*>(Wq + (size_t)a * DQ);
        float acc = 0.0f;
#pragma unroll
        for (int i = 0; i < DQ / 128; ++i) {     // 1024 / (32 lanes * 4) = 8 iters
            float4 w = w4[i * 32 + lane];
            float4 q = sq4[i * 32 + lane];
            acc += w.x * q.x + w.y * q.y + w.z * q.z + w.w * q.w;
        }
#pragma unroll
        for (int o = 16; o; o >>= 1) acc += __shfl_xor_sync(0xFFFFFFFFu, acc, o);
        if (lane == 0) g_pq[b * A + a] = acc;
    }
}

// Fused: score -> p -> alignment -> (sparse) context
__global__ void __launch_bounds__(512) sma_kernel(
    const float* __restrict__ memory,          // [B,T,DV]
    const float* __restrict__ pm,              // [B,T,A]
    const float* __restrict__ prev,            // [B,T]
    const unsigned char* __restrict__ mask,    // [B,T] (bool, 1 byte)
    const float* __restrict__ noise,           // [B,T]
    const float* __restrict__ v_dir,           // [A]
    const float* __restrict__ v_g,             // scalar
    const float* __restrict__ v_bias,          // scalar
    const float* __restrict__ score_bias,      // scalar
    float* ctx,                                // [B,DV] or null -> scratch
    float* align_out)                          // [B,T]  or null -> scratch
{
    if (ctx == nullptr) ctx = g_scr_ctx;
    if (align_out == nullptr) align_out = g_scr_align;

    __shared__ float s_pq[A];
    __shared__ float s_wv[A];
    __shared__ float s_p[TC + 1];
    __shared__ float s_al[TC];
    __shared__ float s_inv;

    const int b   = blockIdx.y;
    const int c   = blockIdx.x;
    const int t0  = c * TC;
    const int tid = threadIdx.x;
    const int lane = tid & 31;
    const int warp = tid >> 5;
    const int nw   = blockDim.x >> 5;   // 16 warps

    // ---- setup: pq row, weight-norm v ----
    if (tid < A) s_pq[tid] = g_pq[b * A + tid];
    if (warp == nw - 1) {
        float v0 = v_dir[lane], v1 = v_dir[lane + 32];
        float v2 = v_dir[lane + 64], v3 = v_dir[lane + 96];
        float ss = v0 * v0 + v1 * v1 + v2 * v2 + v3 * v3;
#pragma unroll
        for (int o = 16; o; o >>= 1) ss += __shfl_xor_sync(0xFFFFFFFFu, ss, o);
        if (lane == 0) s_inv = v_g[0] * rsqrtf(ss);
    }
    __syncthreads();
    if (tid < A) s_wv[tid] = v_dir[tid] * s_inv;
    __syncthreads();

    // ---- Phase A: p for t in [t0-1, t0+TC)  (boundary recompute; no cross-block dep) ----
    const float sb = score_bias[0] + v_bias[0];
    const float4* pq4 = reinterpret_cast<const float4*>(s_pq);
    const float4* wv4 = reinterpret_cast<const float4*>(s_wv);
    const float4 qv = pq4[lane];
    const float4 wv = wv4[lane];
    for (int i = warp; i < TC + 1; i += nw) {
        int t = t0 - 1 + i;
        if (t >= 0) {
            float4 x = reinterpret_cast<const float4*>(pm)[((size_t)b * T + t) * (A / 4) + lane];
            float s = ftanh(x.x + qv.x) * wv.x
                    + ftanh(x.y + qv.y) * wv.y
                    + ftanh(x.z + qv.z) * wv.z
                    + ftanh(x.w + qv.w) * wv.w;
#pragma unroll
            for (int o = 16; o; o >>= 1) s += __shfl_xor_sync(0xFFFFFFFFu, s, o);
            if (lane == 0) {
                float score = sb + s + 2.0f * noise[(size_t)b * T + t];
                s_p[i] = 1.0f / (1.0f + __expf(-score));
            }
        }
    }
    __syncthreads();

    // ---- Phase B: alignment ----
    if (tid < TC) {
        int t = t0 + tid;
        float al = prev[(size_t)b * T + t] * s_p[tid + 1];
        if (t > 0) al += prev[(size_t)b * T + t - 1] * (1.0f - s_p[tid]);
        if (mask[(size_t)b * T + t]) al = 0.0f;
        s_al[tid] = al;
        align_out[(size_t)b * T + t] = al;
    }
    __syncthreads();

    // ---- Phase C: context, skipping exact-zero alignment rows ----
    {
        const int d = tid;  // 512 threads == DV
        const float* memb = memory + ((size_t)b * T + t0) * DV + d;
        float acc = 0.0f;
        bool any = false;
        for (int tt = 0; tt < TC; ++tt) {
            float a = s_al[tt];
            if (a != 0.0f) {           // uniform across block; exact-zero skip is value-preserving
                acc += a * memb[(size_t)tt * DV];
                any = true;
            }
        }
        if (any) atomicAdd(&ctx[(size_t)b * DV + d], acc);
    }
}

extern "C" void kernel_launch(void* const* d_in, const int* in_sizes, int n_in,
                              void* d_out, int out_size) {
    const float*         query  = (const float*)d_in[0];
    const float*         memory = (const float*)d_in[1];
    const float*         pm     = (const float*)d_in[2];
    const float*         prev   = (const float*)d_in[3];
    const unsigned char* mask   = (const unsigned char*)d_in[4];
    const float*         noise  = (const float*)d_in[5];
    const float*         Wq     = (const float*)d_in[6];
    const float*         v_dir  = (const float*)d_in[7];
    const float*         v_g    = (const float*)d_in[8];
    const float*         v_bias = (const float*)d_in[9];
    const float*         sbias  = (const float*)d_in[10];

    float* out = (float*)d_out;
    float* ctx;
    float* align_out;

    if (out_size >= B * DV + B * T) {          // concatenated (context, alignment)
        ctx = out;
        align_out = out + B * DV;
    } else if (out_size == B * T) {            // alignment only
        ctx = nullptr;                         // kernels fall back to __device__ scratch
        align_out = out;
    } else {                                   // context only
        ctx = out;
        align_out = nullptr;
    }

    zero_ctx_kernel<<<(B * DV + 511) / 512, 512>>>(ctx);
    pq_kernel<<<B, 256>>>(query, Wq);
    sma_kernel<<<dim3(NC, B), 512>>>(memory, pm, prev, mask, noise,
                                     v_dir, v_g, v_bias, sbias, ctx, align_out);
}

// round 3
// speedup vs baseline: 2.3233x; 2.3233x over previous
#include <cuda_runtime.h>

// Shapes fixed by setup_inputs()
#define B  64
#define T  1024
#define DQ 1024
#define DV 512
#define A  128

// Fallback scratch (no allocation allowed)
__device__ float g_scr_align[B * T];
__device__ float g_scr_ctx[B * DV];

// tanh via fast exp: tanh(x) = 1 - 2/(exp(2x)+1); stable at both tails
__device__ __forceinline__ float ftanh(float x) {
    return 1.0f - 2.0f / (1.0f + __expf(2.0f * x));
}

// One block per batch. Fully fused: pq GEMV row, weight-norm v, sparse
// score/sigmoid (only where prev != 0), alignment scatter, masked write,
// sparse context reduction with plain store.
__global__ void __launch_bounds__(512) sma_fused_kernel(
    const float* __restrict__ query,           // [B,DQ]
    const float* __restrict__ memory,          // [B,T,DV]
    const float* __restrict__ pm,              // [B,T,A]
    const float* __restrict__ prev,            // [B,T]
    const unsigned char* __restrict__ mask,    // [B,T] (bool, 1 byte)
    const float* __restrict__ noise,           // [B,T]
    const float* __restrict__ Wq,              // [A,DQ]
    const float* __restrict__ v_dir,           // [A]
    const float* __restrict__ v_g,             // scalar
    const float* __restrict__ v_bias,          // scalar
    const float* __restrict__ score_bias,      // scalar
    float* ctx,                                // [B,DV] or null -> scratch
    float* align_out)                          // [B,T]  or null -> scratch
{
    if (ctx == nullptr) ctx = g_scr_ctx;
    if (align_out == nullptr) align_out = g_scr_align;

    __shared__ float s_q[DQ];          // 4 KB
    __shared__ float s_pq[A];
    __shared__ float s_wv[A];
    __shared__ float s_inv;
    __shared__ float s_al[T];          // 4 KB
    __shared__ int   s_nnz;
    __shared__ int   s_t[T];           // 4 KB  nonzero-prev positions
    __shared__ float s_pv[T];          // 4 KB  their prev values
    __shared__ int   s_nnz2;
    __shared__ int   s_t2[T];          // 4 KB  nonzero-alignment positions
    __shared__ float s_av[T];          // 4 KB  their values

    const int b    = blockIdx.x;
    const int tid  = threadIdx.x;
    const int lane = tid & 31;
    const int warp = tid >> 5;         // 16 warps

    // ---- Phase 1: stage query row, zero align buffer, weight-norm scale ----
    for (int i = tid; i < DQ; i += 512) s_q[i] = query[(size_t)b * DQ + i];
    for (int t = tid; t < T;  t += 512) s_al[t] = 0.0f;
    if (tid == 0) { s_nnz = 0; s_nnz2 = 0; }
    if (warp == 15) {
        float v0 = v_dir[lane], v1 = v_dir[lane + 32];
        float v2 = v_dir[lane + 64], v3 = v_dir[lane + 96];
        float ss = v0 * v0 + v1 * v1 + v2 * v2 + v3 * v3;
#pragma unroll
        for (int o = 16; o; o >>= 1) ss += __shfl_xor_sync(0xFFFFFFFFu, ss, o);
        if (lane == 0) s_inv = v_g[0] * rsqrtf(ss);
    }
    __syncthreads();

    // ---- Phase 2: pq[b,a] = query[b,:]·Wq[a,:]  (warp per row, coalesced) ----
    {
        const float4* q4 = reinterpret_cast<const float4*>(s_q);
        for (int a = warp; a < A; a += 16) {
            const float4* w4 = reinterpret_cast<const float4*>(Wq + (size_t)a * DQ);
            float acc = 0.0f;
#pragma unroll
            for (int i = 0; i < DQ / 128; ++i) {   // 8 iters
                float4 w = w4[i * 32 + lane];
                float4 q = q4[i * 32 + lane];
                acc += w.x * q.x + w.y * q.y + w.z * q.z + w.w * q.w;
            }
#pragma unroll
            for (int o = 16; o; o >>= 1) acc += __shfl_xor_sync(0xFFFFFFFFu, acc, o);
            if (lane == 0) s_pq[a] = acc;
        }
    }
    if (tid < A) s_wv[tid] = v_dir[tid] * s_inv;

    // ---- Phase 3: scan prev for nonzero entries (dynamic sparsity) ----
    for (int t = tid; t < T; t += 512) {
        float pv = prev[(size_t)b * T + t];
        if (pv != 0.0f) {
            int idx = atomicAdd(&s_nnz, 1);
            s_t[idx]  = t;
            s_pv[idx] = pv;
        }
    }
    __syncthreads();

    // ---- Phase 4: p = sigmoid(score) only at nonzero-prev t; scatter align ----
    {
        const float sb = score_bias[0] + v_bias[0];
        const float4 qv = reinterpret_cast<const float4*>(s_pq)[lane];
        const float4 wv = reinterpret_cast<const float4*>(s_wv)[lane];
        const int nnz = s_nnz;
        for (int i = warp; i < nnz; i += 16) {
            const int   t  = s_t[i];
            const float pv = s_pv[i];
            float4 x = reinterpret_cast<const float4*>(pm)[((size_t)b * T + t) * (A / 4) + lane];
            float s = ftanh(x.x + qv.x) * wv.x
                    + ftanh(x.y + qv.y) * wv.y
                    + ftanh(x.z + qv.z) * wv.z
                    + ftanh(x.w + qv.w) * wv.w;
#pragma unroll
            for (int o = 16; o; o >>= 1) s += __shfl_xor_sync(0xFFFFFFFFu, s, o);
            if (lane == 0) {
                float score = sb + s + 2.0f * noise[(size_t)b * T + t];
                float p = 1.0f / (1.0f + __expf(-score));
                atomicAdd(&s_al[t], pv * p);                       // prev[t] * p[t]
                if (t + 1 < T) atomicAdd(&s_al[t + 1], pv * (1.0f - p));  // moved
            }
        }
    }
    __syncthreads();

    // ---- Phase 5: mask, write alignment, collect nonzero-align list ----
    for (int t = tid; t < T; t += 512) {
        float v = s_al[t];
        if (mask[(size_t)b * T + t]) v = 0.0f;
        align_out[(size_t)b * T + t] = v;
        if (v != 0.0f) {
            int idx = atomicAdd(&s_nnz2, 1);
            s_t2[idx] = t;
            s_av[idx] = v;
        }
    }
    __syncthreads();

    // ---- Phase 6: context = sum over nonzero alignment rows (exact skip of zeros) ----
    {
        const int d = tid;   // 512 threads == DV
        const int n2 = s_nnz2;
        float acc = 0.0f;
        for (int i = 0; i < n2; ++i) {
            acc += s_av[i] * memory[((size_t)b * T + s_t2[i]) * DV + d];
        }
        ctx[(size_t)b * DV + d] = acc;   // single block owns batch b: plain store
    }
}

extern "C" void kernel_launch(void* const* d_in, const int* in_sizes, int n_in,
                              void* d_out, int out_size) {
    const float*         query  = (const float*)d_in[0];
    const float*         memory = (const float*)d_in[1];
    const float*         pm     = (const float*)d_in[2];
    const float*         prev   = (const float*)d_in[3];
    const unsigned char* mask   = (const unsigned char*)d_in[4];
    const float*         noise  = (const float*)d_in[5];
    const float*         Wq     = (const float*)d_in[6];
    const float*         v_dir  = (const float*)d_in[7];
    const float*         v_g    = (const float*)d_in[8];
    const float*         v_bias = (const float*)d_in[9];
    const float*         sbias  = (const float*)d_in[10];

    float* out = (float*)d_out;
    float* ctx;
    float* align_out;

    if (out_size >= B * DV + B * T) {          // concatenated (context, alignment)
        ctx = out;
        align_out = out + B * DV;
    } else if (out_size == B * T) {            // alignment only
        ctx = nullptr;                         // kernel falls back to __device__ scratch
        align_out = out;
    } else {                                   // context only
        ctx = out;
        align_out = nullptr;
    }

    sma_fused_kernel<<<B, 512>>>(query, memory, pm, prev, mask, noise,
                                 Wq, v_dir, v_g, v_bias, sbias, ctx, align_out);
}

// round 6
// speedup vs baseline: 2.4828x; 1.0687x over previous
#include <cuda_runtime.h>

// Shapes fixed by setup_inputs()
#define B  64
#define T  1024
#define DQ 1024
#define DV 512
#define A  128

#define LIST_CAP 256
#define PM_CAP   4
#define NOISE_CAP 64
#define PF_ROWS  8

// Global scratch (no allocation allowed)
__device__ float g_pq[B * A];
__device__ float g_scr_align[B * T];
__device__ float g_scr_ctx[B * DV];

// tanh via fast exp: tanh(x) = 1 - 2/(exp(2x)+1); stable at both tails
__device__ __forceinline__ float ftanh(float x) {
    return 1.0f - 2.0f / (1.0f + __expf(2.0f * x));
}

// ===================== Node 1: pq[b,a] = query[b,:]·Wq[a,:] =====================
// 64 blocks: (4 a-tiles of 32 rows) x (16 groups of 4 batches). Each block reads
// 128 KB of Wq + 16 KB of query; Wq amortized over 4 batches.
__global__ void __launch_bounds__(512) pq_kernel(const float* __restrict__ query,
                                                 const float* __restrict__ Wq) {
    __shared__ float q[4][DQ];                 // 16 KB
    const int tid  = threadIdx.x;
    const int lane = tid & 31;
    const int warp = tid >> 5;
    const int a_tile = blockIdx.x & 3;
    const int b0     = (blockIdx.x >> 2) * 4;

    float4* q4s = reinterpret_cast<float4*>(&q[0][0]);
    const float4* qg = reinterpret_cast<const float4*>(query + (size_t)b0 * DQ);
    q4s[tid]       = qg[tid];                  // 4 contiguous rows = 1024 float4
    q4s[tid + 512] = qg[tid + 512];
    __syncthreads();

#pragma unroll
    for (int r = 0; r < 2; ++r) {
        const int a = a_tile * 32 + warp + r * 16;
        const float4* w4 = reinterpret_cast<const float4*>(Wq + (size_t)a * DQ);
        float acc0 = 0.f, acc1 = 0.f, acc2 = 0.f, acc3 = 0.f;
#pragma unroll
        for (int i = 0; i < 8; ++i) {
            float4 w  = w4[i * 32 + lane];
            float4 q0 = reinterpret_cast<const float4*>(q[0])[i * 32 + lane];
            float4 q1 = reinterpret_cast<const float4*>(q[1])[i * 32 + lane];
            float4 q2 = reinterpret_cast<const float4*>(q[2])[i * 32 + lane];
            float4 q3 = reinterpret_cast<const float4*>(q[3])[i * 32 + lane];
            acc0 += w.x*q0.x + w.y*q0.y + w.z*q0.z + w.w*q0.w;
            acc1 += w.x*q1.x + w.y*q1.y + w.z*q1.z + w.w*q1.w;
            acc2 += w.x*q2.x + w.y*q2.y + w.z*q2.z + w.w*q2.w;
            acc3 += w.x*q3.x + w.y*q3.y + w.z*q3.z + w.w*q3.w;
        }
#pragma unroll
        for (int o = 16; o; o >>= 1) {
            acc0 += __shfl_xor_sync(0xFFFFFFFFu, acc0, o);
            acc1 += __shfl_xor_sync(0xFFFFFFFFu, acc1, o);
            acc2 += __shfl_xor_sync(0xFFFFFFFFu, acc2, o);
            acc3 += __shfl_xor_sync(0xFFFFFFFFu, acc3, o);
        }
        if (lane == 0) {
            g_pq[(size_t)(b0 + 0) * A + a] = acc0;
            g_pq[(size_t)(b0 + 1) * A + a] = acc1;
            g_pq[(size_t)(b0 + 2) * A + a] = acc2;
            g_pq[(size_t)(b0 + 3) * A + a] = acc3;
        }
    }
}

// ===================== Node 2: fused sparse attention step =====================
struct ConsS {
    float prev[T];                     // 4 KB
    float pfull[T];                    // 4 KB  p at nonzero-prev t (else 0)
    float al[T];                       // 4 KB
    float pq[A];
    float wv[A];
    float pmr[PM_CAP][A];              // prefetched pm rows
    float noise_v[NOISE_CAP];
    float pf[PF_ROWS][DV];             // 16 KB prefetched memory rows
    int   pf_t[PF_ROWS];
    int   t1[LIST_CAP];
    float pv1[LIST_CAP];
    int   t2[LIST_CAP];
    float av2[LIST_CAP];
    unsigned char mk[T];               // 1 KB
    float inv;
    int nnz, nnz2;
};

__global__ void __launch_bounds__(512) sma_kernel(
    const float* __restrict__ memory,          // [B,T,DV]
    const float* __restrict__ pm,              // [B,T,A]
    const float* __restrict__ prev,            // [B,T]
    const unsigned char* __restrict__ mask,    // [B,T]
    const float* __restrict__ noise,           // [B,T]
    const float* __restrict__ v_dir,           // [A]
    const float* __restrict__ v_g,
    const float* __restrict__ v_bias,
    const float* __restrict__ score_bias,
    float* ctx,                                // [B,DV] or null -> scratch
    float* align_out)                          // [B,T]  or null -> scratch
{
    if (ctx == nullptr)       ctx       = g_scr_ctx;
    if (align_out == nullptr) align_out = g_scr_align;

    __shared__ ConsS S;
    const int b    = blockIdx.x;
    const int tid  = threadIdx.x;
    const int lane = tid & 31;
    const int warp = tid >> 5;

    // --- C1: stage prev/mask, zero pfull, weight-norm scale, load pq ---
    if (tid < 256) {
        reinterpret_cast<float4*>(S.prev)[tid] =
            reinterpret_cast<const float4*>(prev + (size_t)b * T)[tid];
        reinterpret_cast<uchar4*>(S.mk)[tid] =
            reinterpret_cast<const uchar4*>(mask + (size_t)b * T)[tid];
    }
    S.pfull[tid]       = 0.f;
    S.pfull[tid + 512] = 0.f;
    if (tid >= 256 && tid < 256 + A) S.pq[tid - 256] = g_pq[(size_t)b * A + (tid - 256)];
    if (warp == 15) {
        float v0 = v_dir[lane], v1 = v_dir[lane + 32];
        float v2 = v_dir[lane + 64], v3 = v_dir[lane + 96];
        float ss = v0*v0 + v1*v1 + v2*v2 + v3*v3;
#pragma unroll
        for (int o = 16; o; o >>= 1) ss += __shfl_xor_sync(0xFFFFFFFFu, ss, o);
        if (lane == 0) S.inv = v_g[0] * rsqrtf(ss);
    }
    __syncthreads();

    // --- C2: deterministic nonzero-prev compaction (warp 0, ascending t) ---
    if (warp == 0) {
        int cnt = 0;
        for (int c0 = 0; c0 < T / 32; ++c0) {
            int t = c0 * 32 + lane;
            float pv = S.prev[t];
            unsigned m = __ballot_sync(0xFFFFFFFFu, pv != 0.f);
            if (pv != 0.f) {
                int pos = cnt + __popc(m & ((1u << lane) - 1u));
                if (pos < LIST_CAP) { S.t1[pos] = t; S.pv1[pos] = pv; }
            }
            cnt += __popc(m);
        }
        if (lane == 0) S.nnz = cnt;
    }
    if (tid < A) S.wv[tid] = v_dir[tid] * S.inv;
    __syncthreads();

    const int  nnz     = S.nnz;
    const bool sparse1 = (nnz <= LIST_CAP);

    // --- C3: prefetch pm/noise/memory rows at nonzero positions (one DRAM trip) ---
    if (sparse1) {
        if (tid < PF_ROWS) {
            int i  = tid >> 1;
            int tt = (i < nnz) ? S.t1[i] + (tid & 1) : -1;
            if (tt >= T) tt = -1;
            S.pf_t[tid] = tt;
        }
        if (tid < NOISE_CAP && tid < nnz)
            S.noise_v[tid] = noise[(size_t)b * T + S.t1[tid]];
    }
    __syncthreads();
    if (sparse1) {
        if (warp < PM_CAP && warp < nnz) {
            reinterpret_cast<float4*>(S.pmr[warp])[lane] =
                reinterpret_cast<const float4*>(pm)[((size_t)b * T + S.t1[warp]) * (A / 4) + lane];
        }
#pragma unroll
        for (int j = 0; j < PF_ROWS; ++j) {
            int tt = S.pf_t[j];
            if (tt >= 0) S.pf[j][tid] = memory[((size_t)b * T + tt) * DV + tid];
        }
    }
    __syncthreads();

    // --- C4: score/sigmoid at needed positions ---
    const float sb = score_bias[0] + v_bias[0];
    const float4 qv  = reinterpret_cast<const float4*>(S.pq)[lane];
    const float4 wvv = reinterpret_cast<const float4*>(S.wv)[lane];
    if (sparse1) {
        for (int i = warp; i < nnz; i += 16) {
            const int t = S.t1[i];
            float4 x = (i < PM_CAP)
                ? reinterpret_cast<const float4*>(S.pmr[i])[lane]
                : reinterpret_cast<const float4*>(pm)[((size_t)b * T + t) * (A / 4) + lane];
            float s = ftanh(x.x + qv.x) * wvv.x
                    + ftanh(x.y + qv.y) * wvv.y
                    + ftanh(x.z + qv.z) * wvv.z
                    + ftanh(x.w + qv.w) * wvv.w;
#pragma unroll
            for (int o = 16; o; o >>= 1) s += __shfl_xor_sync(0xFFFFFFFFu, s, o);
            if (lane == 0) {
                float nz = (i < NOISE_CAP) ? S.noise_v[i] : noise[(size_t)b * T + t];
                float score = sb + s + 2.0f * nz;
                S.pfull[t] = 1.0f / (1.0f + __expf(-score));
            }
        }
    } else {
        for (int t = warp; t < T; t += 16) {
            if (S.prev[t] != 0.f) {
                float4 x = reinterpret_cast<const float4*>(pm)[((size_t)b * T + t) * (A / 4) + lane];
                float s = ftanh(x.x + qv.x) * wvv.x
                        + ftanh(x.y + qv.y) * wvv.y
                        + ftanh(x.z + qv.z) * wvv.z
                        + ftanh(x.w + qv.w) * wvv.w;
#pragma unroll
                for (int o = 16; o; o >>= 1) s += __shfl_xor_sync(0xFFFFFFFFu, s, o);
                if (lane == 0) {
                    float score = sb + s + 2.0f * noise[(size_t)b * T + t];
                    S.pfull[t] = 1.0f / (1.0f + __expf(-score));
                }
            }
        }
    }
    __syncthreads();

    // --- C5: alignment, gather form (deterministic) ---
    for (int t = tid; t < T; t += 512) {
        float pv = S.prev[t];
        float al = (pv != 0.f) ? pv * S.pfull[t] : 0.f;
        if (t > 0) {
            float pv0 = S.prev[t - 1];
            if (pv0 != 0.f) al += pv0 * (1.f - S.pfull[t - 1]);
        }
        if (S.mk[t]) al = 0.f;
        S.al[t] = al;
        align_out[(size_t)b * T + t] = al;
    }
    __syncthreads();

    // --- C6: compact nonzero alignment (warp 0, ascending t) ---
    if (warp == 0) {
        int cnt = 0;
        for (int c0 = 0; c0 < T / 32; ++c0) {
            int t = c0 * 32 + lane;
            float av = S.al[t];
            unsigned m = __ballot_sync(0xFFFFFFFFu, av != 0.f);
            if (av != 0.f) {
                int pos = cnt + __popc(m & ((1u << lane) - 1u));
                if (pos < LIST_CAP) { S.t2[pos] = t; S.av2[pos] = av; }
            }
            cnt += __popc(m);
        }
        if (lane == 0) S.nnz2 = cnt;
    }
    __syncthreads();

    // --- C7: context (512 threads == DV), exact-zero rows skipped ---
    const int n2 = S.nnz2;
    float acc = 0.f;
    if (n2 <= LIST_CAP) {
        for (int i = 0; i < n2; ++i) {
            const int t = S.t2[i];
            int j_hit = -1;
#pragma unroll
            for (int j = 0; j < PF_ROWS; ++j) if (S.pf_t[j] == t) j_hit = j;
            float val = (sparse1 && j_hit >= 0)
                ? S.pf[j_hit][tid]
                : memory[((size_t)b * T + t) * DV + tid];
            acc += S.av2[i] * val;
        }
    } else {
        for (int t = 0; t < T; ++t) {
            float a = S.al[t];
            if (a != 0.f) acc += a * memory[((size_t)b * T + t) * DV + tid];
        }
    }
    ctx[(size_t)b * DV + tid] = acc;
}

extern "C" void kernel_launch(void* const* d_in, const int* in_sizes, int n_in,
                              void* d_out, int out_size) {
    const float*         query  = (const float*)d_in[0];
    const float*         memory = (const float*)d_in[1];
    const float*         pm     = (const float*)d_in[2];
    const float*         prev   = (const float*)d_in[3];
    const unsigned char* mask   = (const unsigned char*)d_in[4];
    const float*         noise  = (const float*)d_in[5];
    const float*         Wq     = (const float*)d_in[6];
    const float*         v_dir  = (const float*)d_in[7];
    const float*         v_g    = (const float*)d_in[8];
    const float*         v_bias = (const float*)d_in[9];
    const float*         sbias  = (const float*)d_in[10];

    float* out = (float*)d_out;
    float* ctx;
    float* align_out;

    if (out_size >= B * DV + B * T) {          // concatenated (context, alignment)
        ctx = out;
        align_out = out + B * DV;
    } else if (out_size == B * T) {            // alignment only
        ctx = nullptr;                         // kernel falls back to __device__ scratch
        align_out = out;
    } else {                                   // context only
        ctx = out;
        align_out = nullptr;
    }

    pq_kernel<<<64, 512>>>(query, Wq);
    sma_kernel<<<B, 512>>>(memory, pm, prev, mask, noise,
                           v_dir, v_g, v_bias, sbias, ctx, align_out);
}

// round 11
// speedup vs baseline: 2.8853x; 1.1621x over previous
#include <cuda_runtime.h>

// Shapes fixed by setup_inputs()
#define B  64
#define T  1024
#define DQ 1024
#define DV 512
#define A  128

#define LIST_CAP 256
#define PM_CAP   4
#define NOISE_CAP 64
#define PF_ROWS  8

// Global scratch (no allocation allowed)
__device__ __align__(16) float g_pq[B * A];
__device__ __align__(16) float g_scr_align[B * T];
__device__ __align__(16) float g_scr_ctx[B * DV];

// tanh via fast exp: tanh(x) = 1 - 2/(exp(2x)+1); stable at both tails
__device__ __forceinline__ float ftanh(float x) {
    return 1.0f - 2.0f / (1.0f + __expf(2.0f * x));
}

// ===================== Node 1: pq[b,a] = query[b,:]·Wq[a,:] =====================
// 64 blocks: (4 a-tiles of 32 rows) x (16 groups of 4 batches). Each block reads
// 128 KB of Wq + 16 KB of query; Wq amortized over 4 batches.
__global__ void __launch_bounds__(512) pq_kernel(const float* __restrict__ query,
                                                 const float* __restrict__ Wq) {
    __shared__ __align__(16) float q[4][DQ];   // 16 KB (only shared var, as in R6)
    const int tid  = threadIdx.x;
    const int lane = tid & 31;
    const int warp = tid >> 5;
    const int a_tile = blockIdx.x & 3;
    const int b0     = (blockIdx.x >> 2) * 4;

    float4* q4s = reinterpret_cast<float4*>(&q[0][0]);
    const float4* qg = reinterpret_cast<const float4*>(query + (size_t)b0 * DQ);
    q4s[tid]       = qg[tid];                  // 4 contiguous rows = 1024 float4
    q4s[tid + 512] = qg[tid + 512];
    __syncthreads();

#pragma unroll
    for (int r = 0; r < 2; ++r) {
        const int a = a_tile * 32 + warp + r * 16;
        const float4* w4 = reinterpret_cast<const float4*>(Wq + (size_t)a * DQ);
        float acc0 = 0.f, acc1 = 0.f, acc2 = 0.f, acc3 = 0.f;
#pragma unroll
        for (int i = 0; i < 8; ++i) {
            float4 w  = w4[i * 32 + lane];
            float4 q0 = reinterpret_cast<const float4*>(q[0])[i * 32 + lane];
            float4 q1 = reinterpret_cast<const float4*>(q[1])[i * 32 + lane];
            float4 q2 = reinterpret_cast<const float4*>(q[2])[i * 32 + lane];
            float4 q3 = reinterpret_cast<const float4*>(q[3])[i * 32 + lane];
            acc0 += w.x*q0.x + w.y*q0.y + w.z*q0.z + w.w*q0.w;
            acc1 += w.x*q1.x + w.y*q1.y + w.z*q1.z + w.w*q1.w;
            acc2 += w.x*q2.x + w.y*q2.y + w.z*q2.z + w.w*q2.w;
            acc3 += w.x*q3.x + w.y*q3.y + w.z*q3.z + w.w*q3.w;
        }
#pragma unroll
        for (int o = 16; o; o >>= 1) {
            acc0 += __shfl_xor_sync(0xFFFFFFFFu, acc0, o);
            acc1 += __shfl_xor_sync(0xFFFFFFFFu, acc1, o);
            acc2 += __shfl_xor_sync(0xFFFFFFFFu, acc2, o);
            acc3 += __shfl_xor_sync(0xFFFFFFFFu, acc3, o);
        }
        if (lane == 0) {
            g_pq[(size_t)(b0 + 0) * A + a] = acc0;
            g_pq[(size_t)(b0 + 1) * A + a] = acc1;
            g_pq[(size_t)(b0 + 2) * A + a] = acc2;
            g_pq[(size_t)(b0 + 3) * A + a] = acc3;
        }
    }
}

// ===================== Node 2: fused sparse attention step =====================
struct __align__(16) ConsS {
    float prev[T];                 // off 0     (float4-cast)
    float pfull[T];                // off 4096
    float al[T];                   // off 8192
    float pq[A];                   // off 12288 (float4-cast)
    float wv[A];                   // off 12800 (float4-cast)
    float pmr[PM_CAP][A];          // off 13312 (float4-cast, row stride 512B)
    float noise_v[NOISE_CAP];      // off 15360
    float pf[PF_ROWS][DV];         // off 15616 (16 KB)
    int   pf_t[PF_ROWS];
    int   t1[LIST_CAP];
    int   t2[LIST_CAP];
    float av2[LIST_CAP];
    unsigned char mk[T];           // 1 KB (uchar4-cast; offset 4B-multiple)
    unsigned words[32];
    int   base[33];
    float inv;
    int   nnz, nnz2;
};

__global__ void __launch_bounds__(512) sma_kernel(
    const float* __restrict__ memory,          // [B,T,DV]
    const float* __restrict__ pm,              // [B,T,A]
    const float* __restrict__ prev,            // [B,T]
    const unsigned char* __restrict__ mask,    // [B,T]
    const float* __restrict__ noise,           // [B,T]
    const float* __restrict__ v_dir,           // [A]
    const float* __restrict__ v_g,
    const float* __restrict__ v_bias,
    const float* __restrict__ score_bias,
    float* ctx,                                // [B,DV] or null -> scratch
    float* align_out)                          // [B,T]  or null -> scratch
{
    if (ctx == nullptr)       ctx       = g_scr_ctx;
    if (align_out == nullptr) align_out = g_scr_align;

    __shared__ ConsS S;
    const int b    = blockIdx.x;
    const int tid  = threadIdx.x;
    const int lane = tid & 31;
    const int warp = tid >> 5;

    // --- C1: stage prev/mask, zero pfull, weight-norm scale, load pq (as in R6) ---
    if (tid < 256) {
        reinterpret_cast<float4*>(S.prev)[tid] =
            reinterpret_cast<const float4*>(prev + (size_t)b * T)[tid];
        reinterpret_cast<uchar4*>(S.mk)[tid] =
            reinterpret_cast<const uchar4*>(mask + (size_t)b * T)[tid];
    }
    S.pfull[tid]       = 0.f;
    S.pfull[tid + 512] = 0.f;
    if (tid >= 256 && tid < 256 + A) S.pq[tid - 256] = g_pq[(size_t)b * A + (tid - 256)];
    if (warp == 15) {
        float v0 = v_dir[lane], v1 = v_dir[lane + 32];
        float v2 = v_dir[lane + 64], v3 = v_dir[lane + 96];
        float ss = v0*v0 + v1*v1 + v2*v2 + v3*v3;
#pragma unroll
        for (int o = 16; o; o >>= 1) ss += __shfl_xor_sync(0xFFFFFFFFu, ss, o);
        if (lane == 0) S.inv = v_g[0] * rsqrtf(ss);
    }
    __syncthreads();

    // --- C2: parallel bitmask compaction of nonzero-prev (ascending t) ---
    {
        const float pa = S.prev[tid];
        const float pb = S.prev[tid + 512];
        const unsigned wa = __ballot_sync(0xFFFFFFFFu, pa != 0.f);
        const unsigned wb = __ballot_sync(0xFFFFFFFFu, pb != 0.f);
        if (lane == 0) { S.words[warp] = wa; S.words[16 + warp] = wb; }
        __syncthreads();
        if (warp == 0) {   // exclusive prefix-scan of word popcounts
            const int c = __popc(S.words[lane]);
            int incl = c;
#pragma unroll
            for (int o = 1; o < 32; o <<= 1) {
                int n = __shfl_up_sync(0xFFFFFFFFu, incl, o);
                if (lane >= o) incl += n;
            }
            S.base[lane] = incl - c;
            if (lane == 31) S.base[32] = incl;
        }
        if (tid < A) S.wv[tid] = v_dir[tid] * S.inv;
        __syncthreads();
        if (pa != 0.f) {
            int pos = S.base[warp] + __popc(wa & ((1u << lane) - 1u));
            if (pos < LIST_CAP) S.t1[pos] = tid;
        }
        if (pb != 0.f) {
            int pos = S.base[16 + warp] + __popc(wb & ((1u << lane) - 1u));
            if (pos < LIST_CAP) S.t1[pos] = tid + 512;
        }
        if (tid == 0) S.nnz = S.base[32];
        __syncthreads();
    }

    const int  nnz     = S.nnz;
    const bool sparse1 = (nnz <= LIST_CAP);

    // --- C3: prefetch pm/noise/memory rows at nonzero positions (as in R6) ---
    if (sparse1) {
        if (tid < PF_ROWS) {
            int i  = tid >> 1;
            int tt = (i < nnz) ? S.t1[i] + (tid & 1) : -1;
            if (tt >= T) tt = -1;
            S.pf_t[tid] = tt;
        }
        if (tid < NOISE_CAP && tid < nnz)
            S.noise_v[tid] = noise[(size_t)b * T + S.t1[tid]];
    }
    __syncthreads();
    if (sparse1) {
        if (warp < PM_CAP && warp < nnz) {
            reinterpret_cast<float4*>(S.pmr[warp])[lane] =
                reinterpret_cast<const float4*>(pm)[((size_t)b * T + S.t1[warp]) * (A / 4) + lane];
        }
#pragma unroll
        for (int j = 0; j < PF_ROWS; ++j) {
            int tt = S.pf_t[j];
            if (tt >= 0) S.pf[j][tid] = memory[((size_t)b * T + tt) * DV + tid];
        }
    }
    __syncthreads();

    // --- C4: score/sigmoid at needed positions (as in R6) ---
    const float sb = score_bias[0] + v_bias[0];
    const float4 qv  = reinterpret_cast<const float4*>(S.pq)[lane];
    const float4 wvv = reinterpret_cast<const float4*>(S.wv)[lane];
    if (sparse1) {
        for (int i = warp; i < nnz; i += 16) {
            const int t = S.t1[i];
            float4 x = (i < PM_CAP)
                ? reinterpret_cast<const float4*>(S.pmr[i])[lane]
                : reinterpret_cast<const float4*>(pm)[((size_t)b * T + t) * (A / 4) + lane];
            float s = ftanh(x.x + qv.x) * wvv.x
                    + ftanh(x.y + qv.y) * wvv.y
                    + ftanh(x.z + qv.z) * wvv.z
                    + ftanh(x.w + qv.w) * wvv.w;
#pragma unroll
            for (int o = 16; o; o >>= 1) s += __shfl_xor_sync(0xFFFFFFFFu, s, o);
            if (lane == 0) {
                float nz = (i < NOISE_CAP) ? S.noise_v[i] : noise[(size_t)b * T + t];
                float score = sb + s + 2.0f * nz;
                S.pfull[t] = 1.0f / (1.0f + __expf(-score));
            }
        }
    } else {
        for (int t = warp; t < T; t += 16) {
            if (S.prev[t] != 0.f) {
                float4 x = reinterpret_cast<const float4*>(pm)[((size_t)b * T + t) * (A / 4) + lane];
                float s = ftanh(x.x + qv.x) * wvv.x
                        + ftanh(x.y + qv.y) * wvv.y
                        + ftanh(x.z + qv.z) * wvv.z
                        + ftanh(x.w + qv.w) * wvv.w;
#pragma unroll
                for (int o = 16; o; o >>= 1) s += __shfl_xor_sync(0xFFFFFFFFu, s, o);
                if (lane == 0) {
                    float score = sb + s + 2.0f * noise[(size_t)b * T + t];
                    S.pfull[t] = 1.0f / (1.0f + __expf(-score));
                }
            }
        }
    }
    __syncthreads();

    // --- C5: alignment (gather form) + parallel compaction of nonzero alignment ---
    float al0, al1;
    {
        const int t = tid;
        float pv = S.prev[t];
        al0 = (pv != 0.f) ? pv * S.pfull[t] : 0.f;
        if (t > 0) {
            float pv0 = S.prev[t - 1];
            if (pv0 != 0.f) al0 += pv0 * (1.f - S.pfull[t - 1]);
        }
        if (S.mk[t]) al0 = 0.f;
        S.al[t] = al0;
        align_out[(size_t)b * T + t] = al0;
    }
    {
        const int t = tid + 512;
        float pv = S.prev[t];
        al1 = (pv != 0.f) ? pv * S.pfull[t] : 0.f;
        {
            float pv0 = S.prev[t - 1];
            if (pv0 != 0.f) al1 += pv0 * (1.f - S.pfull[t - 1]);
        }
        if (S.mk[t]) al1 = 0.f;
        S.al[t] = al1;
        align_out[(size_t)b * T + t] = al1;
    }
    {
        const unsigned wa = __ballot_sync(0xFFFFFFFFu, al0 != 0.f);
        const unsigned wb = __ballot_sync(0xFFFFFFFFu, al1 != 0.f);
        if (lane == 0) { S.words[warp] = wa; S.words[16 + warp] = wb; }
        __syncthreads();
        if (warp == 0) {
            const int c = __popc(S.words[lane]);
            int incl = c;
#pragma unroll
            for (int o = 1; o < 32; o <<= 1) {
                int n = __shfl_up_sync(0xFFFFFFFFu, incl, o);
                if (lane >= o) incl += n;
            }
            S.base[lane] = incl - c;
            if (lane == 31) S.base[32] = incl;
        }
        __syncthreads();
        if (al0 != 0.f) {
            int pos = S.base[warp] + __popc(wa & ((1u << lane) - 1u));
            if (pos < LIST_CAP) { S.t2[pos] = tid; S.av2[pos] = al0; }
        }
        if (al1 != 0.f) {
            int pos = S.base[16 + warp] + __popc(wb & ((1u << lane) - 1u));
            if (pos < LIST_CAP) { S.t2[pos] = tid + 512; S.av2[pos] = al1; }
        }
        if (tid == 0) S.nnz2 = S.base[32];
        __syncthreads();
    }

    // --- C6: context (512 threads == DV), exact-zero rows skipped (as in R6) ---
    const int n2 = S.nnz2;
    float acc = 0.f;
    if (n2 <= LIST_CAP) {
        for (int i = 0; i < n2; ++i) {
            const int t = S.t2[i];
            int j_hit = -1;
#pragma unroll
            for (int j = 0; j < PF_ROWS; ++j) if (S.pf_t[j] == t) j_hit = j;
            float val = (sparse1 && j_hit >= 0)
                ? S.pf[j_hit][tid]
                : memory[((size_t)b * T + t) * DV + tid];
            acc += S.av2[i] * val;
        }
    } else {
        for (int t = 0; t < T; ++t) {
            float a = S.al[t];
            if (a != 0.f) acc += a * memory[((size_t)b * T + t) * DV + tid];
        }
    }
    ctx[(size_t)b * DV + tid] = acc;
}

extern "C" void kernel_launch(void* const* d_in, const int* in_sizes, int n_in,
                              void* d_out, int out_size) {
    const float*         query  = (const float*)d_in[0];
    const float*         memory = (const float*)d_in[1];
    const float*         pm     = (const float*)d_in[2];
    const float*         prev   = (const float*)d_in[3];
    const unsigned char* mask   = (const unsigned char*)d_in[4];
    const float*         noise  = (const float*)d_in[5];
    const float*         Wq     = (const float*)d_in[6];
    const float*         v_dir  = (const float*)d_in[7];
    const float*         v_g    = (const float*)d_in[8];
    const float*         v_bias = (const float*)d_in[9];
    const float*         sbias  = (const float*)d_in[10];

    float* out = (float*)d_out;
    float* ctx;
    float* align_out;

    if (out_size >= B * DV + B * T) {          // concatenated (context, alignment)
        ctx = out;
        align_out = out + B * DV;
    } else if (out_size == B * T) {            // alignment only
        ctx = nullptr;                         // kernel falls back to __device__ scratch
        align_out = out;
    } else {                                   // context only
        ctx = out;
        align_out = nullptr;
    }

    pq_kernel<<<64, 512>>>(query, Wq);
    sma_kernel<<<B, 512>>>(memory, pm, prev, mask, noise,
                           v_dir, v_g, v_bias, sbias, ctx, align_out);
}